// round 9
// baseline (speedup 1.0000x reference)
#include <cuda_runtime.h>
#include <cuda_fp16.h>
#include <math.h>
#include <stdint.h>

// ---------------------------------------------------------------------------
// Problem constants
// ---------------------------------------------------------------------------
#define BB 2
#define CIN 64
#define COUT 96
#define TT 8
#define HH 48
#define WW 48
#define NN (TT*HH*WW)          // 18432
#define K27 27
#define CK (CIN*K27)           // 1728  (kk = k*64 + c ordering)
#define OFFC (3*K27)           // 81
#define BN_TOT (BB*NN)         // 36864
#define NTILE 128
#define NTILES (BN_TOT/NTILE)  // 288
#define NCHUNK K27             // 27 chunks of 64 k-halfs (one tap each)

#define A_STAGE_BYTES 16384    // 128 rows x 128B
#define B_STAGE_BYTES 12288    // 96 rows x 128B
#define STAGE_BYTES   (A_STAGE_BYTES + B_STAGE_BYTES)   // 28672
#define NSTAGE 3
#define SMEM_BYTES (NSTAGE * STAGE_BYTES)               // 86016

// ---------------------------------------------------------------------------
// Static device scratch (all fp16 data paths)
// ---------------------------------------------------------------------------
__device__ __half g_xTh[(size_t)BB * NN * CIN];    // x transposed fp16 [b][n][c]
__device__ __half g_colsh[(size_t)BN_TOT * CK];    // deform im2col fp16
__device__ __half g_wt_off_h[96 * CK];             // offset weights fp16 padded
__device__ __half g_wth[96 * CK];                  // conv weights fp16
__device__ float g_doff[3][(size_t)BB * K27 * NN];
__device__ float g_sum[COUT], g_sqsum[COUT];
__device__ float g_scale[COUT], g_bias[COUT];

// ---------------------------------------------------------------------------
// Helpers
// ---------------------------------------------------------------------------
__device__ __forceinline__ uint32_t smem_u32(const void* p) {
    uint32_t a;
    asm("{ .reg .u64 t; cvta.to.shared.u64 t, %1; cvt.u32.u64 %0, t; }"
        : "=r"(a) : "l"(p));
    return a;
}

__device__ __forceinline__ void cp16(uint32_t dst, const void* src, int sz) {
    asm volatile("cp.async.cg.shared.global [%0], [%1], 16, %2;"
                 :: "r"(dst), "l"(src), "r"(sz) : "memory");
}

#define CP_COMMIT() asm volatile("cp.async.commit_group;" ::: "memory")
#define CP_WAIT1()  asm volatile("cp.async.wait_group 1;" ::: "memory")
#define CP_WAIT0()  asm volatile("cp.async.wait_group 0;" ::: "memory")

__device__ __forceinline__ void ldsm_x4(uint32_t r[4], uint32_t addr) {
    asm volatile("ldmatrix.sync.aligned.m8n8.x4.shared.b16 {%0,%1,%2,%3}, [%4];"
                 : "=r"(r[0]), "=r"(r[1]), "=r"(r[2]), "=r"(r[3]) : "r"(addr));
}

__device__ __forceinline__ void mma_f16(float d[4],
                                        const uint32_t a[4],
                                        const uint32_t b[2]) {
    asm volatile(
        "mma.sync.aligned.m16n8k16.row.col.f32.f16.f16.f32 "
        "{%0,%1,%2,%3}, {%4,%5,%6,%7}, {%8,%9}, {%0,%1,%2,%3};"
        : "+f"(d[0]), "+f"(d[1]), "+f"(d[2]), "+f"(d[3])
        : "r"(a[0]), "r"(a[1]), "r"(a[2]), "r"(a[3]), "r"(b[0]), "r"(b[1]));
}

// ---------------------------------------------------------------------------
// Kernel: transpose x [b][c][n] -> g_xTh [b][n][c] (fp16)
// ---------------------------------------------------------------------------
__global__ void __launch_bounds__(256)
transpose_kernel(const float* __restrict__ x) {
    __shared__ float tile[64][33];
    int n0g = blockIdx.x * 32;
    int b = n0g >= NN;
    int nn = n0g - b * NN;
    int tx = threadIdx.x, ty = threadIdx.y;   // 32 x 8
    const float* xb = x + (size_t)b * CIN * NN;
    #pragma unroll
    for (int cc = 0; cc < 8; cc++) {
        int c = cc * 8 + ty;
        tile[c][tx] = xb[(size_t)c * NN + nn + tx];
    }
    __syncthreads();
    __half2* dst = (__half2*)(g_xTh + ((size_t)b * NN + nn) * CIN);
    #pragma unroll
    for (int q = 0; q < 4; q++) {
        int p = ty * 4 + q;
        dst[p * 32 + tx] =
            __floats2half2_rn(tile[2 * tx][p], tile[2 * tx + 1][p]);
    }
}

// ---------------------------------------------------------------------------
// Kernel: prep — reorder weights [o][c*27+k] -> [o][k*64+c], fp16, pad.
// ---------------------------------------------------------------------------
__global__ void prep_kernel(const float* __restrict__ w_off,
                            const float* __restrict__ w) {
    int i = blockIdx.x * blockDim.x + threadIdx.x;
    if (i < 96 * CK) {
        int o = i / CK, kk = i - o * CK;
        int k = kk >> 6, c = kk & 63;
        int src = c * K27 + k;
        g_wth[i] = __float2half_rn(w[o * CK + src]);
        g_wt_off_h[i] = (o < OFFC) ? __float2half_rn(w_off[o * CK + src])
                                   : __float2half_rn(0.0f);
    }
    if (i < COUT) { g_sum[i] = 0.0f; g_sqsum[i] = 0.0f; }
}

// ---------------------------------------------------------------------------
// Kernel: deformable (trilinear) im2col gather, fp16 chain accumulation.
// 224 threads, one position per block; item = (tap, 8-channel group).
// Two 4-corner __hfma2 chains combined with one __hadd2.
// ---------------------------------------------------------------------------
__global__ void __launch_bounds__(224)
deform_gather_kernel() {
    int bn = blockIdx.x;
    int b = bn >= NN;
    int n = bn - b * NN;
    int t = n / (HH * WW);
    int y = (n / WW) % HH;
    int xx = n % WW;

    __shared__ int2 s_tab[K27][8];   // {uint4-offset, half2 weight bits}

    int tid = threadIdx.x;
    if (tid < K27) {
        int k = tid;
        int kt = k / 9, ky = (k / 3) % 3, kx = k % 3;
        size_t oidx = (size_t)(b * K27 + k) * NN + n;
        float pt = (float)(t + kt - 1) + g_doff[0][oidx];
        float py = (float)(y + ky - 1) + g_doff[1][oidx];
        float px = (float)(xx + kx - 1) + g_doff[2][oidx];
        float tf = floorf(pt), yf = floorf(py), xf = floorf(px);
        int it = (int)tf, iy = (int)yf, ix = (int)xf;
        float ft = pt - tf, fy = py - yf, fx = px - xf;
        #pragma unroll
        for (int j = 0; j < 8; j++) {
            int at = (j >> 2) & 1, ay = (j >> 1) & 1, ax = j & 1;
            int ti = it + at, yi = iy + ay, xi = ix + ax;
            bool valid = (ti >= 0 && ti < TT && yi >= 0 && yi < HH &&
                          xi >= 0 && xi < WW);
            float wv = (at ? ft : 1.0f - ft) * (ay ? fy : 1.0f - fy)
                     * (ax ? fx : 1.0f - fx);
            int off8 = valid ? ((ti * HH + yi) * WW + xi) * 8 : 0;
            __half2 w2 = __float2half2_rn(valid ? wv : 0.0f);
            s_tab[k][j] = make_int2(off8, *(const int*)&w2);
        }
    }
    __syncthreads();

    if (tid < K27 * 8) {
        int k = tid >> 3, c8 = tid & 7;
        const uint4* xb = (const uint4*)(g_xTh + (size_t)b * NN * CIN) + c8;
        __half2 z = __float2half2_rn(0.0f);
        __half2 a0 = z, a1 = z, a2 = z, a3 = z;
        __half2 e0 = z, e1 = z, e2 = z, e3 = z;
        #pragma unroll
        for (int j = 0; j < 8; j++) {
            int2 tc = s_tab[k][j];
            uint4 v = __ldg(xb + tc.x);
            __half2 w2 = *(__half2*)&tc.y;
            const __half2* hp = (const __half2*)&v;
            if (j < 4) {
                a0 = __hfma2(w2, hp[0], a0);
                a1 = __hfma2(w2, hp[1], a1);
                a2 = __hfma2(w2, hp[2], a2);
                a3 = __hfma2(w2, hp[3], a3);
            } else {
                e0 = __hfma2(w2, hp[0], e0);
                e1 = __hfma2(w2, hp[1], e1);
                e2 = __hfma2(w2, hp[2], e2);
                e3 = __hfma2(w2, hp[3], e3);
            }
        }
        uint4 o;
        __half2* op = (__half2*)&o;
        op[0] = __hadd2(a0, e0);
        op[1] = __hadd2(a1, e1);
        op[2] = __hadd2(a2, e2);
        op[3] = __hadd2(a3, e3);
        ((uint4*)(g_colsh + (size_t)bn * CK))[k * 8 + c8] = o;
    }
}

// ---------------------------------------------------------------------------
// GEMM: C[128 pos x 96 ch] per CTA, K=1728, fp16 mma.sync m16n8k16.
// cp.async 3-stage pipeline, XOR-swizzled smem, ldmatrix x4 fragments.
// 256 threads = 8 warps 4(M) x 2(N); warp tile 32 x 48.
// MODE 0: A gathered from g_xTh via dense tap shift (cp.async zfill);
//         B = g_wt_off_h; epilogue tanh -> g_doff.
// MODE 1: A = g_colsh; B = g_wth; epilogue -> out + BN atomics.
// ---------------------------------------------------------------------------
template <int MODE>
__global__ void __launch_bounds__(256, 2)
gemm_cp_kernel(const float* __restrict__ b_off, float* __restrict__ out) {
    extern __shared__ char smem_raw[];
    uint32_t smem_base = smem_u32(smem_raw);

    int tid = threadIdx.x;
    int wid = tid >> 5, lane = tid & 31;
    int gid = lane >> 2, tig = lane & 3;
    int warp_m = wid & 3, warp_n = wid >> 2;
    int n0 = blockIdx.x * NTILE;
    int bb = n0 >= NN;

    const __half* Bmat = (MODE == 0) ? g_wt_off_h : g_wth;

    int c4s = tid & 7;     // granule within row (16B = 8 halfs)
    int row0 = tid >> 3;   // 0..31

    int rt_[4], ry_[4], rx_[4];
    if (MODE == 0) {
        #pragma unroll
        for (int i = 0; i < 4; i++) {
            int n = n0 - bb * NN + row0 + i * 32;
            rt_[i] = n / (HH * WW);
            int r = n % (HH * WW);
            ry_[i] = r / WW;
            rx_[i] = r - ry_[i] * WW;
        }
    }

    auto issue = [&](int chunk) {
        uint32_t stage = (uint32_t)(chunk % NSTAGE) * STAGE_BYTES;
        uint32_t Ab = smem_base + stage;
        uint32_t Bb = Ab + A_STAGE_BYTES;
        if (MODE == 0) {
            int tap = chunk;
            int kt = tap / 9;
            int kr = tap - kt * 9;
            int ky = kr / 3, kx = kr - (kr / 3) * 3;
            #pragma unroll
            for (int i = 0; i < 4; i++) {
                int row = row0 + i * 32;
                int zt = rt_[i] + kt - 1, zy = ry_[i] + ky - 1,
                    zx = rx_[i] + kx - 1;
                bool valid = (zt >= 0 && zt < TT && zy >= 0 && zy < HH &&
                              zx >= 0 && zx < WW);
                int idx = valid ? (bb * NN + (zt * HH + zy) * WW + zx) : 0;
                const __half* src = g_xTh + (size_t)idx * CIN + c4s * 8;
                uint32_t dst = Ab + (row << 7) + ((c4s ^ (row & 7)) << 4);
                cp16(dst, src, valid ? 16 : 0);
            }
        } else {
            #pragma unroll
            for (int i = 0; i < 4; i++) {
                int row = row0 + i * 32;
                const __half* src = g_colsh + (size_t)(n0 + row) * CK
                                  + chunk * 64 + c4s * 8;
                uint32_t dst = Ab + (row << 7) + ((c4s ^ (row & 7)) << 4);
                cp16(dst, src, 16);
            }
        }
        #pragma unroll
        for (int i = 0; i < 3; i++) {
            int col = row0 + i * 32;
            const __half* src = Bmat + (size_t)col * CK + chunk * 64 + c4s * 8;
            uint32_t dst = Bb + (col << 7) + ((c4s ^ (col & 7)) << 4);
            cp16(dst, src, 16);
        }
        CP_COMMIT();
    };

    // accumulators: 2 M-blocks x 6 N-blocks
    float d[2][6][4];
    #pragma unroll
    for (int mt = 0; mt < 2; mt++)
        #pragma unroll
        for (int nt = 0; nt < 6; nt++)
            #pragma unroll
            for (int q = 0; q < 4; q++) d[mt][nt][q] = 0.0f;

    // fragment-load lane geometry
    int a_row_lo = lane & 15;
    int a_hi = lane >> 4;                            // k-granule parity
    // B x4 geometry: lanes 0-7 -> (col +0, g+0), 8-15 -> (+0, g+1),
    //                lanes 16-23 -> (+8, g+0), 24-31 -> (+8, g+1)
    int bx4_col_lo = (lane & 7) + ((lane >> 4) << 3);
    int bx4_hi = (lane >> 3) & 1;

    issue(0);
    issue(1);

    for (int chunk = 0; chunk < NCHUNK; chunk++) {
        if (chunk < NCHUNK - 1) { CP_WAIT1(); } else { CP_WAIT0(); }
        __syncthreads();
        if (chunk + 2 < NCHUNK) issue(chunk + 2);

        uint32_t stage = (uint32_t)(chunk % NSTAGE) * STAGE_BYTES;
        uint32_t Ab = smem_base + stage;
        uint32_t Bb = Ab + A_STAGE_BYTES;

        #pragma unroll
        for (int ks = 0; ks < 4; ks++) {   // 4 k16-steps per 64-half chunk
            uint32_t af[2][4], bf[6][2];
            #pragma unroll
            for (int mt = 0; mt < 2; mt++) {
                int row = warp_m * 32 + mt * 16 + a_row_lo;
                int g = 2 * ks + a_hi;
                uint32_t addr = Ab + (row << 7) + ((g ^ (row & 7)) << 4);
                ldsm_x4(af[mt], addr);
            }
            #pragma unroll
            for (int pr = 0; pr < 3; pr++) {   // 3 column pairs (16 cols)
                int col = warp_n * 48 + pr * 16 + bx4_col_lo;
                int g = 2 * ks + bx4_hi;
                uint32_t addr = Bb + (col << 7) + ((g ^ (col & 7)) << 4);
                uint32_t r4[4];
                ldsm_x4(r4, addr);
                bf[2 * pr][0] = r4[0]; bf[2 * pr][1] = r4[1];
                bf[2 * pr + 1][0] = r4[2]; bf[2 * pr + 1][1] = r4[3];
            }
            #pragma unroll
            for (int mt = 0; mt < 2; mt++)
                #pragma unroll
                for (int nt = 0; nt < 6; nt++)
                    mma_f16(d[mt][nt], af[mt], bf[nt]);
        }
        __syncthreads();
    }

    // ---- epilogue ------------------------------------------------------
    #pragma unroll
    for (int mt = 0; mt < 2; mt++) {
        #pragma unroll
        for (int half = 0; half < 2; half++) {
            int row = warp_m * 32 + mt * 16 + half * 8 + gid;
            int n = n0 - bb * NN + row;
            #pragma unroll
            for (int nt = 0; nt < 6; nt++) {
                #pragma unroll
                for (int e = 0; e < 2; e++) {
                    int col = warp_n * 48 + nt * 8 + tig * 2 + e;
                    float v = d[mt][nt][half * 2 + e];
                    if (MODE == 0) {
                        if (col < OFFC) {
                            int axis = col / K27, kk = col - axis * K27;
                            float sc = axis ? 2.0f : 1.0f;
                            float o = tanhf(v + __ldg(b_off + col)) * sc;
                            g_doff[axis][(size_t)(bb * K27 + kk) * NN + n] = o;
                        }
                    } else {
                        out[(size_t)(bb * COUT + col) * NN + n] = v;
                    }
                }
            }
        }
    }

    // ---- fused BN stats (MODE 1) ---------------------------------------
    if (MODE == 1) {
        #pragma unroll
        for (int nt = 0; nt < 6; nt++) {
            #pragma unroll
            for (int e = 0; e < 2; e++) {
                float s = 0.0f, q = 0.0f;
                #pragma unroll
                for (int mt = 0; mt < 2; mt++)
                    #pragma unroll
                    for (int half = 0; half < 2; half++) {
                        float v = d[mt][nt][half * 2 + e];
                        s += v; q += v * v;
                    }
                #pragma unroll
                for (int off = 16; off >= 4; off >>= 1) {
                    s += __shfl_down_sync(0xffffffffu, s, off);
                    q += __shfl_down_sync(0xffffffffu, q, off);
                }
                if (lane < 4) {
                    int col = warp_n * 48 + nt * 8 + tig * 2 + e;
                    atomicAdd(&g_sum[col], s);
                    atomicAdd(&g_sqsum[col], q);
                }
            }
        }
    }
}

// ---------------------------------------------------------------------------
// BN finalize + apply
// ---------------------------------------------------------------------------
__global__ void bn_finalize_kernel(const float* __restrict__ gamma,
                                   const float* __restrict__ beta) {
    int c = threadIdx.x;
    if (c < COUT) {
        float cnt = (float)(BB * NN);
        float mean = g_sum[c] / cnt;
        float var = g_sqsum[c] / cnt - mean * mean;
        float inv = rsqrtf(var + 1e-5f);
        float sc = gamma[c] * inv;
        g_scale[c] = sc;
        g_bias[c] = beta[c] - mean * sc;
    }
}

__global__ void __launch_bounds__(256)
bn_apply_kernel(float* __restrict__ out) {
    int i4 = blockIdx.x * blockDim.x + threadIdx.x;
    const int TOT4 = BB * COUT * NN / 4;
    if (i4 < TOT4) {
        int c = (i4 / (NN / 4)) % COUT;
        float sc = g_scale[c], bi = g_bias[c];
        float4 v = reinterpret_cast<float4*>(out)[i4];
        v.x = fmaxf(fmaf(v.x, sc, bi), 0.0f);
        v.y = fmaxf(fmaf(v.y, sc, bi), 0.0f);
        v.z = fmaxf(fmaf(v.z, sc, bi), 0.0f);
        v.w = fmaxf(fmaf(v.w, sc, bi), 0.0f);
        reinterpret_cast<float4*>(out)[i4] = v;
    }
}

// ---------------------------------------------------------------------------
extern "C" void kernel_launch(void* const* d_in, const int* in_sizes, int n_in,
                              void* d_out, int out_size) {
    const float* x     = (const float*)d_in[0];
    const float* w_off = (const float*)d_in[1];
    const float* b_off = (const float*)d_in[2];
    const float* w     = (const float*)d_in[3];
    const float* gamma = (const float*)d_in[4];
    const float* beta  = (const float*)d_in[5];
    float* out = (float*)d_out;

    cudaFuncSetAttribute(gemm_cp_kernel<0>,
                         cudaFuncAttributeMaxDynamicSharedMemorySize,
                         SMEM_BYTES);
    cudaFuncSetAttribute(gemm_cp_kernel<1>,
                         cudaFuncAttributeMaxDynamicSharedMemorySize,
                         SMEM_BYTES);

    transpose_kernel<<<BN_TOT / 32, dim3(32, 8)>>>(x);
    prep_kernel<<<(96 * CK + 255) / 256, 256>>>(w_off, w);

    gemm_cp_kernel<0><<<NTILES, 256, SMEM_BYTES>>>(b_off, nullptr);
    deform_gather_kernel<<<BN_TOT, 224>>>();
    gemm_cp_kernel<1><<<NTILES, 256, SMEM_BYTES>>>(nullptr, out);

    bn_finalize_kernel<<<1, 128>>>(gamma, beta);

    const int TOT4 = BB * COUT * NN / 4;
    bn_apply_kernel<<<(TOT4 + 255) / 256, 256>>>(out);
}

// round 10
// speedup vs baseline: 1.0035x; 1.0035x over previous
#include <cuda_runtime.h>
#include <cuda_fp16.h>
#include <math.h>
#include <stdint.h>

// ---------------------------------------------------------------------------
// Problem constants
// ---------------------------------------------------------------------------
#define BB 2
#define CIN 64
#define COUT 96
#define TT 8
#define HH 48
#define WW 48
#define NN (TT*HH*WW)          // 18432
#define K27 27
#define CK (CIN*K27)           // 1728  (kk = k*64 + c ordering)
#define OFFC (3*K27)           // 81
#define BN_TOT (BB*NN)         // 36864
#define NTILE 128
#define NTILES (BN_TOT/NTILE)  // 288
#define NCHUNK K27             // 27 chunks of 64 k-halfs (one tap each)

#define A_STAGE_BYTES 16384    // 128 rows x 128B
#define B_STAGE_BYTES 12288    // 96 rows x 128B
#define STAGE_BYTES   (A_STAGE_BYTES + B_STAGE_BYTES)   // 28672
#define NSTAGE 3
#define SMEM_BYTES (NSTAGE * STAGE_BYTES)               // 86016  (gemm0)
#define TAB_BYTES  (128 * 8 * 8)                        // 8KB corner table
#define SMEM1_BYTES (SMEM_BYTES + TAB_BYTES)            // 94208  (gemm1 fused)

// ---------------------------------------------------------------------------
// Static device scratch (all fp16 data paths)
// ---------------------------------------------------------------------------
__device__ __half g_xTh[(size_t)BB * NN * CIN];    // x transposed fp16 [b][n][c]
__device__ __half g_wt_off_h[96 * CK];             // offset weights fp16 padded
__device__ __half g_wth[96 * CK];                  // conv weights fp16
__device__ float g_doff[3][(size_t)BB * K27 * NN];
__device__ float g_sum[COUT], g_sqsum[COUT];
__device__ float g_scale[COUT], g_bias[COUT];

// ---------------------------------------------------------------------------
// Helpers
// ---------------------------------------------------------------------------
__device__ __forceinline__ uint32_t smem_u32(const void* p) {
    uint32_t a;
    asm("{ .reg .u64 t; cvta.to.shared.u64 t, %1; cvt.u32.u64 %0, t; }"
        : "=r"(a) : "l"(p));
    return a;
}

__device__ __forceinline__ void cp16(uint32_t dst, const void* src, int sz) {
    asm volatile("cp.async.cg.shared.global [%0], [%1], 16, %2;"
                 :: "r"(dst), "l"(src), "r"(sz) : "memory");
}

#define CP_COMMIT() asm volatile("cp.async.commit_group;" ::: "memory")
#define CP_WAIT1()  asm volatile("cp.async.wait_group 1;" ::: "memory")
#define CP_WAIT0()  asm volatile("cp.async.wait_group 0;" ::: "memory")
#define PROD_BAR()  asm volatile("bar.sync 8, 128;" ::: "memory")

__device__ __forceinline__ void ldsm_x4(uint32_t r[4], uint32_t addr) {
    asm volatile("ldmatrix.sync.aligned.m8n8.x4.shared.b16 {%0,%1,%2,%3}, [%4];"
                 : "=r"(r[0]), "=r"(r[1]), "=r"(r[2]), "=r"(r[3]) : "r"(addr));
}

__device__ __forceinline__ void mma_f16(float d[4],
                                        const uint32_t a[4],
                                        const uint32_t b[2]) {
    asm volatile(
        "mma.sync.aligned.m16n8k16.row.col.f32.f16.f16.f32 "
        "{%0,%1,%2,%3}, {%4,%5,%6,%7}, {%8,%9}, {%0,%1,%2,%3};"
        : "+f"(d[0]), "+f"(d[1]), "+f"(d[2]), "+f"(d[3])
        : "r"(a[0]), "r"(a[1]), "r"(a[2]), "r"(a[3]), "r"(b[0]), "r"(b[1]));
}

// ---------------------------------------------------------------------------
// Kernel: transpose x [b][c][n] -> g_xTh [b][n][c] (fp16)
// ---------------------------------------------------------------------------
__global__ void __launch_bounds__(256)
transpose_kernel(const float* __restrict__ x) {
    __shared__ float tile[64][33];
    int n0g = blockIdx.x * 32;
    int b = n0g >= NN;
    int nn = n0g - b * NN;
    int tx = threadIdx.x, ty = threadIdx.y;   // 32 x 8
    const float* xb = x + (size_t)b * CIN * NN;
    #pragma unroll
    for (int cc = 0; cc < 8; cc++) {
        int c = cc * 8 + ty;
        tile[c][tx] = xb[(size_t)c * NN + nn + tx];
    }
    __syncthreads();
    __half2* dst = (__half2*)(g_xTh + ((size_t)b * NN + nn) * CIN);
    #pragma unroll
    for (int q = 0; q < 4; q++) {
        int p = ty * 4 + q;
        dst[p * 32 + tx] =
            __floats2half2_rn(tile[2 * tx][p], tile[2 * tx + 1][p]);
    }
}

// ---------------------------------------------------------------------------
// Kernel: prep — reorder weights [o][c*27+k] -> [o][k*64+c], fp16, pad.
// ---------------------------------------------------------------------------
__global__ void prep_kernel(const float* __restrict__ w_off,
                            const float* __restrict__ w) {
    int i = blockIdx.x * blockDim.x + threadIdx.x;
    if (i < 96 * CK) {
        int o = i / CK, kk = i - o * CK;
        int k = kk >> 6, c = kk & 63;
        int src = c * K27 + k;
        g_wth[i] = __float2half_rn(w[o * CK + src]);
        g_wt_off_h[i] = (o < OFFC) ? __float2half_rn(w_off[o * CK + src])
                                   : __float2half_rn(0.0f);
    }
    if (i < COUT) { g_sum[i] = 0.0f; g_sqsum[i] = 0.0f; }
}

// ---------------------------------------------------------------------------
// GEMM 0 (offset conv): C[128 pos x 96 ch], K=1728, fp16 mma m16n8k16.
// cp.async 3-stage pipeline (A gathered densely via tap shift), ldmatrix,
// 256 threads = 8 warps 4(M) x 2(N). Epilogue: tanh -> g_doff.
// ---------------------------------------------------------------------------
__global__ void __launch_bounds__(256, 2)
gemm0_kernel(const float* __restrict__ b_off) {
    extern __shared__ char smem_raw[];
    uint32_t smem_base = smem_u32(smem_raw);

    int tid = threadIdx.x;
    int wid = tid >> 5, lane = tid & 31;
    int gid = lane >> 2, tig = lane & 3;
    int warp_m = wid & 3, warp_n = wid >> 2;
    int n0 = blockIdx.x * NTILE;
    int bb = n0 >= NN;

    int c4s = tid & 7;     // granule within row (16B = 8 halfs)
    int row0 = tid >> 3;   // 0..31

    int rt_[4], ry_[4], rx_[4];
    #pragma unroll
    for (int i = 0; i < 4; i++) {
        int n = n0 - bb * NN + row0 + i * 32;
        rt_[i] = n / (HH * WW);
        int r = n % (HH * WW);
        ry_[i] = r / WW;
        rx_[i] = r - ry_[i] * WW;
    }

    auto issue = [&](int chunk) {
        uint32_t stage = (uint32_t)(chunk % NSTAGE) * STAGE_BYTES;
        uint32_t Ab = smem_base + stage;
        uint32_t Bb = Ab + A_STAGE_BYTES;
        int tap = chunk;
        int kt = tap / 9;
        int kr = tap - kt * 9;
        int ky = kr / 3, kx = kr - (kr / 3) * 3;
        #pragma unroll
        for (int i = 0; i < 4; i++) {
            int row = row0 + i * 32;
            int zt = rt_[i] + kt - 1, zy = ry_[i] + ky - 1,
                zx = rx_[i] + kx - 1;
            bool valid = (zt >= 0 && zt < TT && zy >= 0 && zy < HH &&
                          zx >= 0 && zx < WW);
            int idx = valid ? (bb * NN + (zt * HH + zy) * WW + zx) : 0;
            const __half* src = g_xTh + (size_t)idx * CIN + c4s * 8;
            uint32_t dst = Ab + (row << 7) + ((c4s ^ (row & 7)) << 4);
            cp16(dst, src, valid ? 16 : 0);
        }
        #pragma unroll
        for (int i = 0; i < 3; i++) {
            int col = row0 + i * 32;
            const __half* src = g_wt_off_h + (size_t)col * CK
                              + chunk * 64 + c4s * 8;
            uint32_t dst = Bb + (col << 7) + ((c4s ^ (col & 7)) << 4);
            cp16(dst, src, 16);
        }
        CP_COMMIT();
    };

    float d[2][6][4];
    #pragma unroll
    for (int mt = 0; mt < 2; mt++)
        #pragma unroll
        for (int nt = 0; nt < 6; nt++)
            #pragma unroll
            for (int q = 0; q < 4; q++) d[mt][nt][q] = 0.0f;

    int a_row_lo = lane & 15;
    int a_hi = lane >> 4;
    int bx4_col_lo = (lane & 7) + ((lane >> 4) << 3);
    int bx4_hi = (lane >> 3) & 1;

    issue(0);
    issue(1);

    for (int chunk = 0; chunk < NCHUNK; chunk++) {
        if (chunk < NCHUNK - 1) { CP_WAIT1(); } else { CP_WAIT0(); }
        __syncthreads();
        if (chunk + 2 < NCHUNK) issue(chunk + 2);

        uint32_t stage = (uint32_t)(chunk % NSTAGE) * STAGE_BYTES;
        uint32_t Ab = smem_base + stage;
        uint32_t Bb = Ab + A_STAGE_BYTES;

        #pragma unroll
        for (int ks = 0; ks < 4; ks++) {
            uint32_t af[2][4], bf[6][2];
            #pragma unroll
            for (int mt = 0; mt < 2; mt++) {
                int row = warp_m * 32 + mt * 16 + a_row_lo;
                int g = 2 * ks + a_hi;
                uint32_t addr = Ab + (row << 7) + ((g ^ (row & 7)) << 4);
                ldsm_x4(af[mt], addr);
            }
            #pragma unroll
            for (int pr = 0; pr < 3; pr++) {
                int col = warp_n * 48 + pr * 16 + bx4_col_lo;
                int g = 2 * ks + bx4_hi;
                uint32_t addr = Bb + (col << 7) + ((g ^ (col & 7)) << 4);
                uint32_t r4[4];
                ldsm_x4(r4, addr);
                bf[2 * pr][0] = r4[0]; bf[2 * pr][1] = r4[1];
                bf[2 * pr + 1][0] = r4[2]; bf[2 * pr + 1][1] = r4[3];
            }
            #pragma unroll
            for (int mt = 0; mt < 2; mt++)
                #pragma unroll
                for (int nt = 0; nt < 6; nt++)
                    mma_f16(d[mt][nt], af[mt], bf[nt]);
        }
        __syncthreads();
    }

    #pragma unroll
    for (int mt = 0; mt < 2; mt++) {
        #pragma unroll
        for (int half = 0; half < 2; half++) {
            int row = warp_m * 32 + mt * 16 + half * 8 + gid;
            int n = n0 - bb * NN + row;
            #pragma unroll
            for (int nt = 0; nt < 6; nt++) {
                #pragma unroll
                for (int e = 0; e < 2; e++) {
                    int col = warp_n * 48 + nt * 8 + tig * 2 + e;
                    if (col < OFFC) {
                        int axis = col / K27, kk = col - axis * K27;
                        float sc = axis ? 2.0f : 1.0f;
                        float v = d[mt][nt][half * 2 + e];
                        float o = tanhf(v + __ldg(b_off + col)) * sc;
                        g_doff[axis][(size_t)(bb * K27 + kk) * NN + n] = o;
                    }
                }
            }
        }
    }
}

// ---------------------------------------------------------------------------
// GEMM 1 (deformable conv), warp-specialized producer/consumer fusion.
// 384 threads: warps 0-7 = MMA consumers (identical layout to gemm0),
//              warps 8-11 = gather producers.
// Per chunk (one tap): producers build the 8-corner table for their 128
// positions (1 thread/position), bar.sync, then gather A[128x64h] straight
// from g_xTh with hfma2 chains and STS into stage (chunk+2)%3. Consumers
// cp.async B, run MMAs on stage chunk. One __syncthreads per chunk.
// Epilogue: out + fused BN atomics.
// ---------------------------------------------------------------------------
__global__ void __launch_bounds__(384, 1)
gemm1_fused_kernel(float* __restrict__ out) {
    extern __shared__ char smem_raw[];
    uint32_t smem_base = smem_u32(smem_raw);
    int2* s_tab = (int2*)(smem_raw + NSTAGE * STAGE_BYTES);  // [128][8]

    int tid = threadIdx.x;
    int n0 = blockIdx.x * NTILE;
    int bb = n0 >= NN;
    bool consumer = tid < 256;

    // ===== producer-side persistent state =====
    int ptid = tid - 256;              // 0..127 (producers only)
    int p_t = 0, p_y = 0, p_x = 0, p_n = 0;
    if (!consumer) {
        p_n = n0 - bb * NN + ptid;
        p_t = p_n / (HH * WW);
        int r = p_n % (HH * WW);
        p_y = r / WW;
        p_x = r - p_y * WW;
    }

    auto make_table = [&](int tap) {   // producers; thread = position ptid
        int kt = tap / 9;
        int kr = tap - kt * 9;
        int ky = kr / 3, kx = kr - (kr / 3) * 3;
        size_t oidx = (size_t)(bb * K27 + tap) * NN + p_n;
        float pt = (float)(p_t + kt - 1) + g_doff[0][oidx];
        float py = (float)(p_y + ky - 1) + g_doff[1][oidx];
        float px = (float)(p_x + kx - 1) + g_doff[2][oidx];
        float tf = floorf(pt), yf = floorf(py), xf = floorf(px);
        int it = (int)tf, iy = (int)yf, ix = (int)xf;
        float ft = pt - tf, fy = py - yf, fx = px - xf;
        #pragma unroll
        for (int j = 0; j < 8; j++) {
            int at = (j >> 2) & 1, ay = (j >> 1) & 1, ax = j & 1;
            int ti = it + at, yi = iy + ay, xi = ix + ax;
            bool valid = (ti >= 0 && ti < TT && yi >= 0 && yi < HH &&
                          xi >= 0 && xi < WW);
            float wv = (at ? ft : 1.0f - ft) * (ay ? fy : 1.0f - fy)
                     * (ax ? fx : 1.0f - fx);
            int off8 = valid ? ((ti * HH + yi) * WW + xi) : 0;
            __half2 w2 = __float2half2_rn(valid ? wv : 0.0f);
            s_tab[ptid * 8 + j] = make_int2(off8, *(const int*)&w2);
        }
    };

    auto gather = [&](int chunk) {     // producers; 8 items each
        char* Astage = smem_raw + (chunk % NSTAGE) * STAGE_BYTES;
        const uint4* xb = (const uint4*)(g_xTh + (size_t)bb * NN * CIN);
        int c8 = ptid & 7;
        int pos0 = ptid >> 3;          // 0..15
        #pragma unroll
        for (int i = 0; i < 8; i++) {
            int pos = pos0 + i * 16;
            __half2 z = __float2half2_rn(0.0f);
            __half2 a0 = z, a1 = z, a2 = z, a3 = z;
            __half2 e0 = z, e1 = z, e2 = z, e3 = z;
            #pragma unroll
            for (int j = 0; j < 8; j++) {
                int2 tc = s_tab[pos * 8 + j];
                uint4 v = __ldg(xb + (size_t)tc.x * 8 + c8);
                __half2 w2 = *(__half2*)&tc.y;
                const __half2* hp = (const __half2*)&v;
                if (j < 4) {
                    a0 = __hfma2(w2, hp[0], a0);
                    a1 = __hfma2(w2, hp[1], a1);
                    a2 = __hfma2(w2, hp[2], a2);
                    a3 = __hfma2(w2, hp[3], a3);
                } else {
                    e0 = __hfma2(w2, hp[0], e0);
                    e1 = __hfma2(w2, hp[1], e1);
                    e2 = __hfma2(w2, hp[2], e2);
                    e3 = __hfma2(w2, hp[3], e3);
                }
            }
            uint4 o;
            __half2* op = (__half2*)&o;
            op[0] = __hadd2(a0, e0);
            op[1] = __hadd2(a1, e1);
            op[2] = __hadd2(a2, e2);
            op[3] = __hadd2(a3, e3);
            *(uint4*)(Astage + (pos << 7) + ((c8 ^ (pos & 7)) << 4)) = o;
        }
    };

    // ===== consumer-side state =====
    int wid = tid >> 5, lane = tid & 31;
    int gid = lane >> 2, tig = lane & 3;
    int warp_m = wid & 3, warp_n = wid >> 2;
    int c4s = tid & 7;
    int row0 = tid >> 3;   // 0..31 for consumers

    auto issueB = [&](int chunk) {
        uint32_t Bb = smem_base + (uint32_t)(chunk % NSTAGE) * STAGE_BYTES
                    + A_STAGE_BYTES;
        #pragma unroll
        for (int i = 0; i < 3; i++) {
            int col = row0 + i * 32;
            const __half* src = g_wth + (size_t)col * CK + chunk * 64 + c4s * 8;
            uint32_t dst = Bb + (col << 7) + ((c4s ^ (col & 7)) << 4);
            cp16(dst, src, 16);
        }
        CP_COMMIT();
    };

    float d[2][6][4];
    #pragma unroll
    for (int mt = 0; mt < 2; mt++)
        #pragma unroll
        for (int nt = 0; nt < 6; nt++)
            #pragma unroll
            for (int q = 0; q < 4; q++) d[mt][nt][q] = 0.0f;

    int a_row_lo = lane & 15;
    int a_hi = lane >> 4;
    int bx4_col_lo = (lane & 7) + ((lane >> 4) << 3);
    int bx4_hi = (lane >> 3) & 1;

    // ===== prologue =====
    if (consumer) {
        issueB(0);
        issueB(1);
    } else {
        make_table(0); PROD_BAR();
        gather(0);     PROD_BAR();
        make_table(1); PROD_BAR();
        gather(1);
    }
    __syncthreads();

    // ===== main loop =====
    for (int chunk = 0; chunk < NCHUNK; chunk++) {
        if (consumer) {
            if (chunk < NCHUNK - 1) { CP_WAIT1(); } else { CP_WAIT0(); }
        }
        __syncthreads();

        if (consumer) {
            if (chunk + 2 < NCHUNK) issueB(chunk + 2);

            uint32_t Ab = smem_base + (uint32_t)(chunk % NSTAGE) * STAGE_BYTES;
            uint32_t Bb = Ab + A_STAGE_BYTES;
            #pragma unroll
            for (int ks = 0; ks < 4; ks++) {
                uint32_t af[2][4], bf[6][2];
                #pragma unroll
                for (int mt = 0; mt < 2; mt++) {
                    int row = warp_m * 32 + mt * 16 + a_row_lo;
                    int g = 2 * ks + a_hi;
                    uint32_t addr = Ab + (row << 7) + ((g ^ (row & 7)) << 4);
                    ldsm_x4(af[mt], addr);
                }
                #pragma unroll
                for (int pr = 0; pr < 3; pr++) {
                    int col = warp_n * 48 + pr * 16 + bx4_col_lo;
                    int g = 2 * ks + bx4_hi;
                    uint32_t addr = Bb + (col << 7) + ((g ^ (col & 7)) << 4);
                    uint32_t r4[4];
                    ldsm_x4(r4, addr);
                    bf[2 * pr][0] = r4[0]; bf[2 * pr][1] = r4[1];
                    bf[2 * pr + 1][0] = r4[2]; bf[2 * pr + 1][1] = r4[3];
                }
                #pragma unroll
                for (int mt = 0; mt < 2; mt++)
                    #pragma unroll
                    for (int nt = 0; nt < 6; nt++)
                        mma_f16(d[mt][nt], af[mt], bf[nt]);
            }
        } else {
            if (chunk + 2 < NCHUNK) {
                make_table(chunk + 2);
                PROD_BAR();
                gather(chunk + 2);
            }
        }
    }

    if (!consumer) return;

    // ===== epilogue (consumers) =====
    #pragma unroll
    for (int mt = 0; mt < 2; mt++) {
        #pragma unroll
        for (int half = 0; half < 2; half++) {
            int row = warp_m * 32 + mt * 16 + half * 8 + gid;
            int n = n0 - bb * NN + row;
            #pragma unroll
            for (int nt = 0; nt < 6; nt++) {
                #pragma unroll
                for (int e = 0; e < 2; e++) {
                    int col = warp_n * 48 + nt * 8 + tig * 2 + e;
                    float v = d[mt][nt][half * 2 + e];
                    out[(size_t)(bb * COUT + col) * NN + n] = v;
                }
            }
        }
    }

    #pragma unroll
    for (int nt = 0; nt < 6; nt++) {
        #pragma unroll
        for (int e = 0; e < 2; e++) {
            float s = 0.0f, q = 0.0f;
            #pragma unroll
            for (int mt = 0; mt < 2; mt++)
                #pragma unroll
                for (int half = 0; half < 2; half++) {
                    float v = d[mt][nt][half * 2 + e];
                    s += v; q += v * v;
                }
            #pragma unroll
            for (int off = 16; off >= 4; off >>= 1) {
                s += __shfl_down_sync(0xffffffffu, s, off);
                q += __shfl_down_sync(0xffffffffu, q, off);
            }
            if (lane < 4) {
                int col = warp_n * 48 + nt * 8 + tig * 2 + e;
                atomicAdd(&g_sum[col], s);
                atomicAdd(&g_sqsum[col], q);
            }
        }
    }
}

// ---------------------------------------------------------------------------
// BN finalize + apply
// ---------------------------------------------------------------------------
__global__ void bn_finalize_kernel(const float* __restrict__ gamma,
                                   const float* __restrict__ beta) {
    int c = threadIdx.x;
    if (c < COUT) {
        float cnt = (float)(BB * NN);
        float mean = g_sum[c] / cnt;
        float var = g_sqsum[c] / cnt - mean * mean;
        float inv = rsqrtf(var + 1e-5f);
        float sc = gamma[c] * inv;
        g_scale[c] = sc;
        g_bias[c] = beta[c] - mean * sc;
    }
}

__global__ void __launch_bounds__(256)
bn_apply_kernel(float* __restrict__ out) {
    int i4 = blockIdx.x * blockDim.x + threadIdx.x;
    const int TOT4 = BB * COUT * NN / 4;
    if (i4 < TOT4) {
        int c = (i4 / (NN / 4)) % COUT;
        float sc = g_scale[c], bi = g_bias[c];
        float4 v = reinterpret_cast<float4*>(out)[i4];
        v.x = fmaxf(fmaf(v.x, sc, bi), 0.0f);
        v.y = fmaxf(fmaf(v.y, sc, bi), 0.0f);
        v.z = fmaxf(fmaf(v.z, sc, bi), 0.0f);
        v.w = fmaxf(fmaf(v.w, sc, bi), 0.0f);
        reinterpret_cast<float4*>(out)[i4] = v;
    }
}

// ---------------------------------------------------------------------------
extern "C" void kernel_launch(void* const* d_in, const int* in_sizes, int n_in,
                              void* d_out, int out_size) {
    const float* x     = (const float*)d_in[0];
    const float* w_off = (const float*)d_in[1];
    const float* b_off = (const float*)d_in[2];
    const float* w     = (const float*)d_in[3];
    const float* gamma = (const float*)d_in[4];
    const float* beta  = (const float*)d_in[5];
    float* out = (float*)d_out;

    cudaFuncSetAttribute(gemm0_kernel,
                         cudaFuncAttributeMaxDynamicSharedMemorySize,
                         SMEM_BYTES);
    cudaFuncSetAttribute(gemm1_fused_kernel,
                         cudaFuncAttributeMaxDynamicSharedMemorySize,
                         SMEM1_BYTES);

    transpose_kernel<<<BN_TOT / 32, dim3(32, 8)>>>(x);
    prep_kernel<<<(96 * CK + 255) / 256, 256>>>(w_off, w);

    gemm0_kernel<<<NTILES, 256, SMEM_BYTES>>>(b_off);
    gemm1_fused_kernel<<<NTILES, 384, SMEM1_BYTES>>>(out);

    bn_finalize_kernel<<<1, 128>>>(gamma, beta);

    const int TOT4 = BB * COUT * NN / 4;
    bn_apply_kernel<<<(TOT4 + 255) / 256, 256>>>(out);
}

// round 11
// speedup vs baseline: 1.0479x; 1.0442x over previous
#include <cuda_runtime.h>
#include <cuda_fp16.h>
#include <math.h>
#include <stdint.h>

// ---------------------------------------------------------------------------
// Problem constants
// ---------------------------------------------------------------------------
#define BB 2
#define CIN 64
#define COUT 96
#define TT 8
#define HH 48
#define WW 48
#define NN (TT*HH*WW)          // 18432
#define K27 27
#define CK (CIN*K27)           // 1728  (kk = k*64 + c ordering)
#define OFFC (3*K27)           // 81
#define BN_TOT (BB*NN)         // 36864
#define NTILE 128
#define NTILES (BN_TOT/NTILE)  // 288
#define NCHUNK K27             // 27 chunks of 64 k-halfs (one tap each)

#define A_STAGE_BYTES 16384    // 128 rows x 128B
#define B_STAGE_BYTES 12288    // 96 rows x 128B
#define STAGE_BYTES   (A_STAGE_BYTES + B_STAGE_BYTES)   // 28672
#define NSTAGE 3
#define SMEM_BYTES (NSTAGE * STAGE_BYTES)               // 86016

// ---------------------------------------------------------------------------
// Static device scratch (all fp16 data paths)
// ---------------------------------------------------------------------------
__device__ __half g_xTh[(size_t)BB * NN * CIN];    // x transposed fp16 [b][n][c]
__device__ __half g_colsh[(size_t)BN_TOT * CK];    // deform im2col fp16
__device__ __half g_wt_off_h[96 * CK];             // offset weights fp16 padded
__device__ __half g_wth[96 * CK];                  // conv weights fp16
__device__ float g_doff[3][(size_t)BB * K27 * NN];
__device__ float g_sum[COUT], g_sqsum[COUT];
__device__ float g_scale[COUT], g_bias[COUT];

// ---------------------------------------------------------------------------
// Helpers
// ---------------------------------------------------------------------------
__device__ __forceinline__ uint32_t smem_u32(const void* p) {
    uint32_t a;
    asm("{ .reg .u64 t; cvta.to.shared.u64 t, %1; cvt.u32.u64 %0, t; }"
        : "=r"(a) : "l"(p));
    return a;
}

__device__ __forceinline__ void cp16(uint32_t dst, const void* src, int sz) {
    asm volatile("cp.async.cg.shared.global [%0], [%1], 16, %2;"
                 :: "r"(dst), "l"(src), "r"(sz) : "memory");
}

#define CP_COMMIT() asm volatile("cp.async.commit_group;" ::: "memory")
#define CP_WAIT1()  asm volatile("cp.async.wait_group 1;" ::: "memory")
#define CP_WAIT0()  asm volatile("cp.async.wait_group 0;" ::: "memory")

__device__ __forceinline__ void ldsm_x4(uint32_t r[4], uint32_t addr) {
    asm volatile("ldmatrix.sync.aligned.m8n8.x4.shared.b16 {%0,%1,%2,%3}, [%4];"
                 : "=r"(r[0]), "=r"(r[1]), "=r"(r[2]), "=r"(r[3]) : "r"(addr));
}

__device__ __forceinline__ void mma_f16(float d[4],
                                        const uint32_t a[4],
                                        const uint32_t b[2]) {
    asm volatile(
        "mma.sync.aligned.m16n8k16.row.col.f32.f16.f16.f32 "
        "{%0,%1,%2,%3}, {%4,%5,%6,%7}, {%8,%9}, {%0,%1,%2,%3};"
        : "+f"(d[0]), "+f"(d[1]), "+f"(d[2]), "+f"(d[3])
        : "r"(a[0]), "r"(a[1]), "r"(a[2]), "r"(a[3]), "r"(b[0]), "r"(b[1]));
}

// ---------------------------------------------------------------------------
// Kernel: transpose x [b][c][n] -> g_xTh [b][n][c] (fp16)
// ---------------------------------------------------------------------------
__global__ void __launch_bounds__(256)
transpose_kernel(const float* __restrict__ x) {
    __shared__ float tile[64][33];
    int n0g = blockIdx.x * 32;
    int b = n0g >= NN;
    int nn = n0g - b * NN;
    int tx = threadIdx.x, ty = threadIdx.y;   // 32 x 8
    const float* xb = x + (size_t)b * CIN * NN;
    #pragma unroll
    for (int cc = 0; cc < 8; cc++) {
        int c = cc * 8 + ty;
        tile[c][tx] = xb[(size_t)c * NN + nn + tx];
    }
    __syncthreads();
    __half2* dst = (__half2*)(g_xTh + ((size_t)b * NN + nn) * CIN);
    #pragma unroll
    for (int q = 0; q < 4; q++) {
        int p = ty * 4 + q;
        dst[p * 32 + tx] =
            __floats2half2_rn(tile[2 * tx][p], tile[2 * tx + 1][p]);
    }
}

// ---------------------------------------------------------------------------
// Kernel: prep — reorder weights [o][c*27+k] -> [o][k*64+c], fp16, pad.
// ---------------------------------------------------------------------------
__global__ void prep_kernel(const float* __restrict__ w_off,
                            const float* __restrict__ w) {
    int i = blockIdx.x * blockDim.x + threadIdx.x;
    if (i < 96 * CK) {
        int o = i / CK, kk = i - o * CK;
        int k = kk >> 6, c = kk & 63;
        int src = c * K27 + k;
        g_wth[i] = __float2half_rn(w[o * CK + src]);
        g_wt_off_h[i] = (o < OFFC) ? __float2half_rn(w_off[o * CK + src])
                                   : __float2half_rn(0.0f);
    }
    if (i < COUT) { g_sum[i] = 0.0f; g_sqsum[i] = 0.0f; }
}

// ---------------------------------------------------------------------------
// Kernel: deformable (trilinear) im2col gather.
// Round-8 shape (128 threads, 1 position/block, 2 items/thread) with
// round-9 micro-opts: packed int2 table (one LDS.64/corner) and
// fp16 hfma2 chain accumulation (two 4-corner chains + hadd2).
// ---------------------------------------------------------------------------
__global__ void __launch_bounds__(128)
deform_gather_kernel() {
    int bn = blockIdx.x;
    int b = bn >= NN;
    int n = bn - b * NN;
    int t = n / (HH * WW);
    int y = (n / WW) % HH;
    int xx = n % WW;

    __shared__ int2 s_tab[K27][8];   // {uint4-offset (idx*8), half2 weight}

    int tid = threadIdx.x;
    if (tid < K27) {
        int k = tid;
        int kt = k / 9, ky = (k / 3) % 3, kx = k % 3;
        size_t oidx = (size_t)(b * K27 + k) * NN + n;
        float pt = (float)(t + kt - 1) + g_doff[0][oidx];
        float py = (float)(y + ky - 1) + g_doff[1][oidx];
        float px = (float)(xx + kx - 1) + g_doff[2][oidx];
        float tf = floorf(pt), yf = floorf(py), xf = floorf(px);
        int it = (int)tf, iy = (int)yf, ix = (int)xf;
        float ft = pt - tf, fy = py - yf, fx = px - xf;
        #pragma unroll
        for (int j = 0; j < 8; j++) {
            int at = (j >> 2) & 1, ay = (j >> 1) & 1, ax = j & 1;
            int ti = it + at, yi = iy + ay, xi = ix + ax;
            bool valid = (ti >= 0 && ti < TT && yi >= 0 && yi < HH &&
                          xi >= 0 && xi < WW);
            float wv = (at ? ft : 1.0f - ft) * (ay ? fy : 1.0f - fy)
                     * (ax ? fx : 1.0f - fx);
            int off8 = valid ? ((ti * HH + yi) * WW + xi) * 8 : 0;
            __half2 w2 = __float2half2_rn(valid ? wv : 0.0f);
            s_tab[k][j] = make_int2(off8, *(const int*)&w2);
        }
    }
    __syncthreads();

    uint4* dst = (uint4*)(g_colsh + (size_t)bn * CK);
    #pragma unroll
    for (int i = 0; i < 2; i++) {
        int u = tid + i * 128;
        if (u < K27 * 8) {
            int k = u >> 3, c8 = u & 7;
            const uint4* xb = (const uint4*)(g_xTh + (size_t)b * NN * CIN) + c8;
            int2 tc[8];
            uint4 v[8];
            #pragma unroll
            for (int j = 0; j < 8; j++) tc[j] = s_tab[k][j];
            #pragma unroll
            for (int j = 0; j < 8; j++) v[j] = __ldg(xb + tc[j].x);
            __half2 z = __float2half2_rn(0.0f);
            __half2 a0 = z, a1 = z, a2 = z, a3 = z;
            __half2 e0 = z, e1 = z, e2 = z, e3 = z;
            #pragma unroll
            for (int j = 0; j < 8; j++) {
                __half2 w2 = *(__half2*)&tc[j].y;
                const __half2* hp = (const __half2*)&v[j];
                if (j < 4) {
                    a0 = __hfma2(w2, hp[0], a0);
                    a1 = __hfma2(w2, hp[1], a1);
                    a2 = __hfma2(w2, hp[2], a2);
                    a3 = __hfma2(w2, hp[3], a3);
                } else {
                    e0 = __hfma2(w2, hp[0], e0);
                    e1 = __hfma2(w2, hp[1], e1);
                    e2 = __hfma2(w2, hp[2], e2);
                    e3 = __hfma2(w2, hp[3], e3);
                }
            }
            uint4 o;
            __half2* op = (__half2*)&o;
            op[0] = __hadd2(a0, e0);
            op[1] = __hadd2(a1, e1);
            op[2] = __hadd2(a2, e2);
            op[3] = __hadd2(a3, e3);
            dst[k * 8 + c8] = o;
        }
    }
}

// ---------------------------------------------------------------------------
// GEMM: C[128 pos x 96 ch] per CTA, K=1728, fp16 mma.sync m16n8k16.
// cp.async 3-stage pipeline, XOR-swizzled smem, ldmatrix x4 fragments.
// 256 threads = 8 warps 4(M) x 2(N); warp tile 32 x 48.
// MODE 0: A gathered from g_xTh via dense tap shift (cp.async zfill);
//         B = g_wt_off_h; epilogue tanh -> g_doff.
//         Skips nt==5 for warp_n==1 (cols 88-95 are zero padding).
// MODE 1: A = g_colsh; B = g_wth; epilogue -> out + BN atomics.
// ---------------------------------------------------------------------------
template <int MODE>
__global__ void __launch_bounds__(256, 2)
gemm_cp_kernel(const float* __restrict__ b_off, float* __restrict__ out) {
    extern __shared__ char smem_raw[];
    uint32_t smem_base = smem_u32(smem_raw);

    int tid = threadIdx.x;
    int wid = tid >> 5, lane = tid & 31;
    int gid = lane >> 2, tig = lane & 3;
    int warp_m = wid & 3, warp_n = wid >> 2;
    int n0 = blockIdx.x * NTILE;
    int bb = n0 >= NN;

    const __half* Bmat = (MODE == 0) ? g_wt_off_h : g_wth;

    int c4s = tid & 7;     // granule within row (16B = 8 halfs)
    int row0 = tid >> 3;   // 0..31

    int rt_[4], ry_[4], rx_[4];
    if (MODE == 0) {
        #pragma unroll
        for (int i = 0; i < 4; i++) {
            int n = n0 - bb * NN + row0 + i * 32;
            rt_[i] = n / (HH * WW);
            int r = n % (HH * WW);
            ry_[i] = r / WW;
            rx_[i] = r - ry_[i] * WW;
        }
    }

    auto issue = [&](int chunk) {
        uint32_t stage = (uint32_t)(chunk % NSTAGE) * STAGE_BYTES;
        uint32_t Ab = smem_base + stage;
        uint32_t Bb = Ab + A_STAGE_BYTES;
        if (MODE == 0) {
            int tap = chunk;
            int kt = tap / 9;
            int kr = tap - kt * 9;
            int ky = kr / 3, kx = kr - (kr / 3) * 3;
            #pragma unroll
            for (int i = 0; i < 4; i++) {
                int row = row0 + i * 32;
                int zt = rt_[i] + kt - 1, zy = ry_[i] + ky - 1,
                    zx = rx_[i] + kx - 1;
                bool valid = (zt >= 0 && zt < TT && zy >= 0 && zy < HH &&
                              zx >= 0 && zx < WW);
                int idx = valid ? (bb * NN + (zt * HH + zy) * WW + zx) : 0;
                const __half* src = g_xTh + (size_t)idx * CIN + c4s * 8;
                uint32_t dst = Ab + (row << 7) + ((c4s ^ (row & 7)) << 4);
                cp16(dst, src, valid ? 16 : 0);
            }
        } else {
            #pragma unroll
            for (int i = 0; i < 4; i++) {
                int row = row0 + i * 32;
                const __half* src = g_colsh + (size_t)(n0 + row) * CK
                                  + chunk * 64 + c4s * 8;
                uint32_t dst = Ab + (row << 7) + ((c4s ^ (row & 7)) << 4);
                cp16(dst, src, 16);
            }
        }
        #pragma unroll
        for (int i = 0; i < 3; i++) {
            int col = row0 + i * 32;
            const __half* src = Bmat + (size_t)col * CK + chunk * 64 + c4s * 8;
            uint32_t dst = Bb + (col << 7) + ((c4s ^ (col & 7)) << 4);
            cp16(dst, src, 16);
        }
        CP_COMMIT();
    };

    // accumulators: 2 M-blocks x 6 N-blocks
    float d[2][6][4];
    #pragma unroll
    for (int mt = 0; mt < 2; mt++)
        #pragma unroll
        for (int nt = 0; nt < 6; nt++)
            #pragma unroll
            for (int q = 0; q < 4; q++) d[mt][nt][q] = 0.0f;

    // fragment-load lane geometry
    int a_row_lo = lane & 15;
    int a_hi = lane >> 4;
    int bx4_col_lo = (lane & 7) + ((lane >> 4) << 3);
    int bx4_hi = (lane >> 3) & 1;

    issue(0);
    issue(1);

    for (int chunk = 0; chunk < NCHUNK; chunk++) {
        if (chunk < NCHUNK - 1) { CP_WAIT1(); } else { CP_WAIT0(); }
        __syncthreads();
        if (chunk + 2 < NCHUNK) issue(chunk + 2);

        uint32_t stage = (uint32_t)(chunk % NSTAGE) * STAGE_BYTES;
        uint32_t Ab = smem_base + stage;
        uint32_t Bb = Ab + A_STAGE_BYTES;

        #pragma unroll
        for (int ks = 0; ks < 4; ks++) {   // 4 k16-steps per 64-half chunk
            uint32_t af[2][4], bf[6][2];
            #pragma unroll
            for (int mt = 0; mt < 2; mt++) {
                int row = warp_m * 32 + mt * 16 + a_row_lo;
                int g = 2 * ks + a_hi;
                uint32_t addr = Ab + (row << 7) + ((g ^ (row & 7)) << 4);
                ldsm_x4(af[mt], addr);
            }
            #pragma unroll
            for (int pr = 0; pr < 3; pr++) {   // 3 column pairs (16 cols)
                int col = warp_n * 48 + pr * 16 + bx4_col_lo;
                int g = 2 * ks + bx4_hi;
                uint32_t addr = Bb + (col << 7) + ((g ^ (col & 7)) << 4);
                uint32_t r4[4];
                ldsm_x4(r4, addr);
                bf[2 * pr][0] = r4[0]; bf[2 * pr][1] = r4[1];
                bf[2 * pr + 1][0] = r4[2]; bf[2 * pr + 1][1] = r4[3];
            }
            #pragma unroll
            for (int mt = 0; mt < 2; mt++)
                #pragma unroll
                for (int nt = 0; nt < 6; nt++) {
                    // MODE 0: cols 88-95 (warp_n==1, nt==5) are zero padding
                    if (MODE == 0 && nt == 5) {
                        if (warp_n == 0)
                            mma_f16(d[mt][nt], af[mt], bf[nt]);
                    } else {
                        mma_f16(d[mt][nt], af[mt], bf[nt]);
                    }
                }
        }
        __syncthreads();
    }

    // ---- epilogue ------------------------------------------------------
    #pragma unroll
    for (int mt = 0; mt < 2; mt++) {
        #pragma unroll
        for (int half = 0; half < 2; half++) {
            int row = warp_m * 32 + mt * 16 + half * 8 + gid;
            int n = n0 - bb * NN + row;
            #pragma unroll
            for (int nt = 0; nt < 6; nt++) {
                #pragma unroll
                for (int e = 0; e < 2; e++) {
                    int col = warp_n * 48 + nt * 8 + tig * 2 + e;
                    float v = d[mt][nt][half * 2 + e];
                    if (MODE == 0) {
                        if (col < OFFC) {
                            int axis = col / K27, kk = col - axis * K27;
                            float sc = axis ? 2.0f : 1.0f;
                            float o = tanhf(v + __ldg(b_off + col)) * sc;
                            g_doff[axis][(size_t)(bb * K27 + kk) * NN + n] = o;
                        }
                    } else {
                        out[(size_t)(bb * COUT + col) * NN + n] = v;
                    }
                }
            }
        }
    }

    // ---- fused BN stats (MODE 1) ---------------------------------------
    if (MODE == 1) {
        #pragma unroll
        for (int nt = 0; nt < 6; nt++) {
            #pragma unroll
            for (int e = 0; e < 2; e++) {
                float s = 0.0f, q = 0.0f;
                #pragma unroll
                for (int mt = 0; mt < 2; mt++)
                    #pragma unroll
                    for (int half = 0; half < 2; half++) {
                        float v = d[mt][nt][half * 2 + e];
                        s += v; q += v * v;
                    }
                #pragma unroll
                for (int off = 16; off >= 4; off >>= 1) {
                    s += __shfl_down_sync(0xffffffffu, s, off);
                    q += __shfl_down_sync(0xffffffffu, q, off);
                }
                if (lane < 4) {
                    int col = warp_n * 48 + nt * 8 + tig * 2 + e;
                    atomicAdd(&g_sum[col], s);
                    atomicAdd(&g_sqsum[col], q);
                }
            }
        }
    }
}

// ---------------------------------------------------------------------------
// BN finalize + apply
// ---------------------------------------------------------------------------
__global__ void bn_finalize_kernel(const float* __restrict__ gamma,
                                   const float* __restrict__ beta) {
    int c = threadIdx.x;
    if (c < COUT) {
        float cnt = (float)(BB * NN);
        float mean = g_sum[c] / cnt;
        float var = g_sqsum[c] / cnt - mean * mean;
        float inv = rsqrtf(var + 1e-5f);
        float sc = gamma[c] * inv;
        g_scale[c] = sc;
        g_bias[c] = beta[c] - mean * sc;
    }
}

__global__ void __launch_bounds__(256)
bn_apply_kernel(float* __restrict__ out) {
    int i4 = blockIdx.x * blockDim.x + threadIdx.x;
    const int TOT4 = BB * COUT * NN / 4;
    if (i4 < TOT4) {
        int c = (i4 / (NN / 4)) % COUT;
        float sc = g_scale[c], bi = g_bias[c];
        float4 v = reinterpret_cast<float4*>(out)[i4];
        v.x = fmaxf(fmaf(v.x, sc, bi), 0.0f);
        v.y = fmaxf(fmaf(v.y, sc, bi), 0.0f);
        v.z = fmaxf(fmaf(v.z, sc, bi), 0.0f);
        v.w = fmaxf(fmaf(v.w, sc, bi), 0.0f);
        reinterpret_cast<float4*>(out)[i4] = v;
    }
}

// ---------------------------------------------------------------------------
extern "C" void kernel_launch(void* const* d_in, const int* in_sizes, int n_in,
                              void* d_out, int out_size) {
    const float* x     = (const float*)d_in[0];
    const float* w_off = (const float*)d_in[1];
    const float* b_off = (const float*)d_in[2];
    const float* w     = (const float*)d_in[3];
    const float* gamma = (const float*)d_in[4];
    const float* beta  = (const float*)d_in[5];
    float* out = (float*)d_out;

    cudaFuncSetAttribute(gemm_cp_kernel<0>,
                         cudaFuncAttributeMaxDynamicSharedMemorySize,
                         SMEM_BYTES);
    cudaFuncSetAttribute(gemm_cp_kernel<1>,
                         cudaFuncAttributeMaxDynamicSharedMemorySize,
                         SMEM_BYTES);

    transpose_kernel<<<BN_TOT / 32, dim3(32, 8)>>>(x);
    prep_kernel<<<(96 * CK + 255) / 256, 256>>>(w_off, w);

    gemm_cp_kernel<0><<<NTILES, 256, SMEM_BYTES>>>(b_off, nullptr);
    deform_gather_kernel<<<BN_TOT, 128>>>();
    gemm_cp_kernel<1><<<NTILES, 256, SMEM_BYTES>>>(nullptr, out);

    bn_finalize_kernel<<<1, 128>>>(gamma, beta);

    const int TOT4 = BB * COUT * NN / 4;
    bn_apply_kernel<<<(TOT4 + 255) / 256, 256>>>(out);
}